// round 9
// baseline (speedup 1.0000x reference)
#include <cuda_runtime.h>
#include <cuda_fp16.h>
#include <math.h>
#include <stdint.h>

// Problem shape (fixed by reference): B=4, S=2048, D=1024
#define BATCH 4
#define SEQ   2048
#define DIM   1024
#define NTOK  (BATCH * SEQ)   // 8192

// ---------------------------------------------------------------------------
// Scratch (static device globals)
// ---------------------------------------------------------------------------
__device__ __half g_xh[NTOK * DIM];
__device__ __half g_Wqkh[2048 * DIM];                        // [Qw^T; Kw^T] hi
__device__ __half g_Wvh[DIM * DIM];                          // Vw^T hi
__device__ __half g_QKh[NTOK * 2048];                        // Q | K (hi only)
__device__ __half g_Vth[DIM * NTOK];                         // V^T [D, NTOK] hi
__device__ __half g_Sh[BATCH * SEQ * SEQ];                   // raw fp16 scores
__device__ __half g_Ph[BATCH * SEQ * SEQ];                   // probs

// ---------------------------------------------------------------------------
// Helpers
// ---------------------------------------------------------------------------
__device__ __forceinline__ uint32_t smem_u32(const void* p) {
    uint32_t a;
    asm("{ .reg .u64 t; cvta.to.shared.u64 t, %1; cvt.u32.u64 %0, t; }" : "=r"(a) : "l"(p));
    return a;
}

#define CP16(dst, src) \
    asm volatile("cp.async.cg.shared.global [%0], [%1], 16;" :: "r"(dst), "l"(src))

#define LDSM4(r, addr) \
    asm volatile("ldmatrix.sync.aligned.m8n8.x4.shared.b16 {%0,%1,%2,%3}, [%4];" \
        : "=r"((r)[0]), "=r"((r)[1]), "=r"((r)[2]), "=r"((r)[3]) : "r"(addr))

// fp32-accumulate MMA
#define MMA4(c, a, b0, b1) \
    asm volatile("mma.sync.aligned.m16n8k16.row.col.f32.f16.f16.f32 " \
        "{%0,%1,%2,%3}, {%4,%5,%6,%7}, {%8,%9}, {%0,%1,%2,%3};" \
        : "+f"((c)[0]), "+f"((c)[1]), "+f"((c)[2]), "+f"((c)[3]) \
        : "r"((a)[0]), "r"((a)[1]), "r"((a)[2]), "r"((a)[3]), "r"(b0), "r"(b1))

// ---------------------------------------------------------------------------
// Projection GEMM: C[M,N] = A[M,K] @ B[N,K]^T, fp16 in / fp16 out (hi only).
// CTA tile 256x128, BK=32, 512 threads = 16 warps (4x4), warp tile 64x32.
// 4-stage cp.async pipeline.
// ---------------------------------------------------------------------------
#define TILE_AB 20480              // 256 rows * 80B pitch  (A tile)
#define TILE_BB 10240              // 128 rows * 80B pitch  (B tile)
#define STAGE_P (TILE_AB + TILE_BB)
#define SMEM_PROJ (4 * STAGE_P)    // 122880

__global__ void __launch_bounds__(512, 1)
gemm_proj(const __half* __restrict__ Ah, const __half* __restrict__ Bh,
          __half* __restrict__ Ch, int K, int lda, int ldb, int ldc)
{
    const int brow0 = blockIdx.y * 256;
    const int bcol0 = blockIdx.x * 128;

    extern __shared__ char sm[];
    const uint32_t smb = smem_u32(sm);

    const int tid = threadIdx.x;
    const int lane = tid & 31;
    const int wid = tid >> 5;     // 0..15
    const int wr = wid >> 2;      // 0..3 -> rows wr*64
    const int wc = wid & 3;       // 0..3 -> cols wc*32

    const int nsteps = K >> 5;

    const int lrow = tid >> 2;    // 0..127
    const int lcol = tid & 3;
    const uint32_t soA1 = (uint32_t)(lrow * 80 + lcol * 16);
    const uint32_t soA2 = (uint32_t)((lrow + 128) * 80 + lcol * 16);
    const uint32_t soB  = soA1;

    auto load_stage = [&](int slot, int k0) {
        uint32_t st = smb + slot * STAGE_P;
        long gk = k0 + lcol * 8;
        CP16(st + soA1,           Ah + (long)(brow0 + lrow)       * lda + gk);
        CP16(st + soA2,           Ah + (long)(brow0 + lrow + 128) * lda + gk);
        CP16(st + TILE_AB + soB,  Bh + (long)(bcol0 + lrow)       * ldb + gk);
        asm volatile("cp.async.commit_group;");
    };

    float acc[4][4][4];
#pragma unroll
    for (int mt = 0; mt < 4; mt++)
#pragma unroll
        for (int nt = 0; nt < 4; nt++)
#pragma unroll
            for (int v = 0; v < 4; v++) acc[mt][nt][v] = 0.f;

    const int arow = lane & 15;
    const int asel = lane >> 4;
    const int browi = (lane & 7) + ((lane >> 4) << 3);
    const int bsel = (lane >> 3) & 1;

#pragma unroll
    for (int k = 0; k < 3; k++) {
        if (k < nsteps) load_stage(k, k * 32);
        else asm volatile("cp.async.commit_group;");
    }

    for (int s = 0; s < nsteps; s++) {
        asm volatile("cp.async.wait_group 2;");
        __syncthreads();

        const uint32_t st = smb + (s & 3) * STAGE_P;
#pragma unroll
        for (int kk = 0; kk < 2; kk++) {
            uint32_t aH[4][4];
#pragma unroll
            for (int mt = 0; mt < 4; mt++) {
                uint32_t off = (uint32_t)((wr * 64 + mt * 16 + arow) * 80 + kk * 32 + asel * 16);
                LDSM4(aH[mt], st + off);
            }
            uint32_t bH[2][4];
#pragma unroll
            for (int np = 0; np < 2; np++) {
                uint32_t off = (uint32_t)((wc * 32 + np * 16 + browi) * 80 + kk * 32 + bsel * 16);
                LDSM4(bH[np], st + TILE_AB + off);
            }
#pragma unroll
            for (int mt = 0; mt < 4; mt++)
#pragma unroll
                for (int nt = 0; nt < 4; nt++) {
                    const int np = nt >> 1, hv = (nt & 1) * 2;
                    MMA4(acc[mt][nt], aH[mt], bH[np][hv], bH[np][hv + 1]);
                }
        }

        if (s + 3 < nsteps) load_stage((s + 3) & 3, (s + 3) * 32);
        else asm volatile("cp.async.commit_group;");
    }

    // epilogue: fp16 hi only
    const int erow = lane >> 2;
    const int ecol = (lane & 3) * 2;
#pragma unroll
    for (int mt = 0; mt < 4; mt++) {
        const int row = brow0 + wr * 64 + mt * 16 + erow;
#pragma unroll
        for (int nt = 0; nt < 4; nt++) {
            const int col = bcol0 + wc * 32 + nt * 8 + ecol;
            const float* c = acc[mt][nt];
            *(__half2*)(Ch + (long)row * ldc + col) =
                __halves2half2(__float2half_rn(c[0]), __float2half_rn(c[1]));
            *(__half2*)(Ch + (long)(row + 8) * ldc + col) =
                __halves2half2(__float2half_rn(c[2]), __float2half_rn(c[3]));
        }
    }
}

// ---------------------------------------------------------------------------
// Attention GEMM (scores / PV): C[M,N] = A[M,K] @ B[N,K]^T, fp16 single
// product. CTA tile 128x128, BK=32, 8 warps (2x4), warp tile 64x32.
// __launch_bounds__(256,2): cap regs at 128 so 2 CTAs co-reside per SM.
// MODE: 1 causal block-skip (heavy rows first); 2 K clamped to brow0+128
//       (heavy rows first).
// EPI:  0 -> fp32 C;  2 -> fp16 hi only.
// ---------------------------------------------------------------------------
#define TILE_B 10240               // 128 rows * 80B pitch
#define SMEM_ATT (4 * 2 * TILE_B)  // 81920

template <int MODE, int EPI>
__global__ void __launch_bounds__(256, 2)
gemm_att(const __half* __restrict__ Ah, const __half* __restrict__ Bh,
         float* __restrict__ C, __half* __restrict__ Ch,
         int K, int lda, int ldb, int ldc,
         long sA, long sB, long sC)
{
    const int by = gridDim.y - 1 - blockIdx.y;   // heavy rows first
    const int brow0 = by * 128;
    const int bcol0 = blockIdx.x * 128;
    if (MODE == 1 && bcol0 > brow0) return;

    extern __shared__ char sm[];
    const uint32_t smb = smem_u32(sm);

    const int tid = threadIdx.x;
    const int lane = tid & 31;
    const int wid = tid >> 5;
    const int wr = wid >> 2;
    const int wc = wid & 3;

    Ah += (long)blockIdx.z * sA;
    Bh += (long)blockIdx.z * sB;

    const int kend = (MODE == 2) ? (brow0 + 128) : K;
    const int nsteps = kend >> 5;

    const int lrow = tid >> 2;
    const int lcol = tid & 3;
    const uint32_t so1 = (uint32_t)(lrow * 80 + lcol * 16);
    const uint32_t so2 = (uint32_t)((lrow + 64) * 80 + lcol * 16);

    auto load_stage = [&](int slot, int k0) {
        uint32_t st = smb + slot * (2 * TILE_B);
        long gk = k0 + lcol * 8;
        CP16(st + so1,          Ah + (long)(brow0 + lrow)      * lda + gk);
        CP16(st + so2,          Ah + (long)(brow0 + lrow + 64) * lda + gk);
        CP16(st + TILE_B + so1, Bh + (long)(bcol0 + lrow)      * ldb + gk);
        CP16(st + TILE_B + so2, Bh + (long)(bcol0 + lrow + 64) * ldb + gk);
        asm volatile("cp.async.commit_group;");
    };

    float acc[4][4][4];
#pragma unroll
    for (int mt = 0; mt < 4; mt++)
#pragma unroll
        for (int nt = 0; nt < 4; nt++)
#pragma unroll
            for (int v = 0; v < 4; v++) acc[mt][nt][v] = 0.f;

    const int arow = lane & 15;
    const int asel = lane >> 4;
    const int browi = (lane & 7) + ((lane >> 4) << 3);
    const int bsel = (lane >> 3) & 1;

#pragma unroll
    for (int k = 0; k < 3; k++) {
        if (k < nsteps) load_stage(k, k * 32);
        else asm volatile("cp.async.commit_group;");
    }

    for (int s = 0; s < nsteps; s++) {
        asm volatile("cp.async.wait_group 2;");
        __syncthreads();

        const uint32_t st = smb + (s & 3) * (2 * TILE_B);
#pragma unroll
        for (int kk = 0; kk < 2; kk++) {
            uint32_t aH[4][4];
#pragma unroll
            for (int mt = 0; mt < 4; mt++) {
                uint32_t off = (uint32_t)((wr * 64 + mt * 16 + arow) * 80 + kk * 32 + asel * 16);
                LDSM4(aH[mt], st + off);
            }
            uint32_t bH[2][4];
#pragma unroll
            for (int np = 0; np < 2; np++) {
                uint32_t off = (uint32_t)((wc * 32 + np * 16 + browi) * 80 + kk * 32 + bsel * 16);
                LDSM4(bH[np], st + TILE_B + off);
            }
#pragma unroll
            for (int mt = 0; mt < 4; mt++)
#pragma unroll
                for (int nt = 0; nt < 4; nt++) {
                    const int np = nt >> 1, hv = (nt & 1) * 2;
                    MMA4(acc[mt][nt], aH[mt], bH[np][hv], bH[np][hv + 1]);
                }
        }

        if (s + 3 < nsteps) load_stage((s + 3) & 3, (s + 3) * 32);
        else asm volatile("cp.async.commit_group;");
    }

    const int erow = lane >> 2;
    const int ecol = (lane & 3) * 2;
#pragma unroll
    for (int mt = 0; mt < 4; mt++) {
        const int row = brow0 + wr * 64 + mt * 16 + erow;
#pragma unroll
        for (int nt = 0; nt < 4; nt++) {
            const int col = bcol0 + wc * 32 + nt * 8 + ecol;
            const float* c = acc[mt][nt];
            if (EPI == 0) {
                float* Cb = C + (long)blockIdx.z * sC;
                *(float2*)(Cb + (long)row * ldc + col)       = make_float2(c[0], c[1]);
                *(float2*)(Cb + (long)(row + 8) * ldc + col) = make_float2(c[2], c[3]);
            } else {
                __half* Hb = Ch + (long)blockIdx.z * sC;
                *(__half2*)(Hb + (long)row * ldc + col) =
                    __halves2half2(__float2half_rn(c[0]), __float2half_rn(c[1]));
                *(__half2*)(Hb + (long)(row + 8) * ldc + col) =
                    __halves2half2(__float2half_rn(c[2]), __float2half_rn(c[3]));
            }
        }
    }
}

// ---------------------------------------------------------------------------
// Elementwise fp32 -> fp16 (hi only).
// ---------------------------------------------------------------------------
__global__ void __launch_bounds__(256)
cvt_hi(const float* __restrict__ in, __half* __restrict__ hi, long n4)
{
    long i = (long)blockIdx.x * blockDim.x + threadIdx.x;
    long stride = (long)gridDim.x * blockDim.x;
    for (; i < n4; i += stride) {
        float4 v = ((const float4*)in)[i];
        __half h[4] = {__float2half_rn(v.x), __float2half_rn(v.y),
                       __float2half_rn(v.z), __float2half_rn(v.w)};
        ((uint2*)hi)[i] = *(uint2*)h;
    }
}

// ---------------------------------------------------------------------------
// Batched weight transpose: z=0 Qw, z=1 Kw -> Wqkh; z=2 Vw -> Wvh.
// ---------------------------------------------------------------------------
__global__ void __launch_bounds__(256)
transpose_w(const float* __restrict__ Qw, const float* __restrict__ Kw,
            const float* __restrict__ Vw, __half* __restrict__ Wqkh,
            __half* __restrict__ Wvh)
{
    __shared__ float tile[32][33];
    const int z = blockIdx.z;
    const float* src = (z == 0) ? Qw : (z == 1) ? Kw : Vw;
    __half* dst = (z == 0) ? Wqkh : (z == 1) ? (Wqkh + DIM * DIM) : Wvh;

    const int c0 = blockIdx.x * 32, r0 = blockIdx.y * 32;
#pragma unroll
    for (int dy = threadIdx.y; dy < 32; dy += 8)
        tile[dy][threadIdx.x] = src[(long)(r0 + dy) * DIM + c0 + threadIdx.x];
    __syncthreads();
#pragma unroll
    for (int dy = threadIdx.y; dy < 32; dy += 8) {
        float v = tile[threadIdx.x][dy];
        dst[(long)(c0 + dy) * DIM + r0 + threadIdx.x] = __float2half_rn(v);
    }
}

// ---------------------------------------------------------------------------
// Causal row softmax, vectorized: fp16 raw scores -> fp16 probs.
// ---------------------------------------------------------------------------
__global__ void __launch_bounds__(256)
softmax_causal(const __half* __restrict__ S, __half* __restrict__ Ph)
{
    const int q = blockIdx.x;
    const int b = blockIdx.y;
    const long rowoff = ((long)b * SEQ + q) * SEQ;
    const __half* row = S + rowoff;
    __half* ph = Ph + rowoff;
    const int n = q + 1;
    const int nblk = ((q >> 7) + 1) << 7;
    const float scale = 0.03125f;  // 1/sqrt(1024)

    const int tid = threadIdx.x;
    const int nch = n >> 3;
    const int tail0 = nch << 3;
    const bool active = tid < nch;
    const bool hastail = (tail0 + tid) < n;

    float vals[8];
    float m = -1e30f;
    if (active) {
        uint4 u = ((const uint4*)row)[tid];
        const __half2* hp = (const __half2*)&u;
#pragma unroll
        for (int i = 0; i < 4; i++) {
            float2 f = __half22float2(hp[i]);
            vals[2 * i]     = f.x * scale;
            vals[2 * i + 1] = f.y * scale;
            m = fmaxf(m, fmaxf(vals[2 * i], vals[2 * i + 1]));
        }
    }
    float tval = -1e30f;
    if (hastail) { tval = __half2float(row[tail0 + tid]) * scale; m = fmaxf(m, tval); }

    __shared__ float red[256];
    red[tid] = m;
    __syncthreads();
#pragma unroll
    for (int s = 128; s > 0; s >>= 1) {
        if (tid < s) red[tid] = fmaxf(red[tid], red[tid + s]);
        __syncthreads();
    }
    m = red[0];
    __syncthreads();

    float sum = 0.f;
    if (active) {
#pragma unroll
        for (int i = 0; i < 8; i++) { vals[i] = __expf(vals[i] - m); sum += vals[i]; }
    }
    float te = 0.f;
    if (hastail) { te = __expf(tval - m); sum += te; }

    red[tid] = sum;
    __syncthreads();
#pragma unroll
    for (int s = 128; s > 0; s >>= 1) {
        if (tid < s) red[tid] += red[tid + s];
        __syncthreads();
    }
    const float inv = 1.0f / red[0];

    if (active) {
        uint4 o;
        __half2* op = (__half2*)&o;
#pragma unroll
        for (int i = 0; i < 4; i++)
            op[i] = __halves2half2(__float2half_rn(vals[2 * i] * inv),
                                   __float2half_rn(vals[2 * i + 1] * inv));
        ((uint4*)ph)[tid] = o;
    }
    if (hastail) ph[tail0 + tid] = __float2half_rn(te * inv);
    const __half z = __float2half_rn(0.f);
    for (int j = n + tid; j < nblk; j += 256) ph[j] = z;
}

// ---------------------------------------------------------------------------
// Host launcher
// ---------------------------------------------------------------------------
extern "C" void kernel_launch(void* const* d_in, const int* in_sizes, int n_in,
                              void* d_out, int out_size)
{
    (void)in_sizes; (void)n_in; (void)out_size;
    const float* x  = (const float*)d_in[0];
    const float* Qw = (const float*)d_in[1];
    const float* Kw = (const float*)d_in[2];
    const float* Vw = (const float*)d_in[3];
    float* out = (float*)d_out;

    __half *xh, *Wqkh, *Wvh, *QKh, *Vth, *Sh, *Ph;
    cudaGetSymbolAddress((void**)&xh,   g_xh);
    cudaGetSymbolAddress((void**)&Wqkh, g_Wqkh);
    cudaGetSymbolAddress((void**)&Wvh,  g_Wvh);
    cudaGetSymbolAddress((void**)&QKh,  g_QKh);
    cudaGetSymbolAddress((void**)&Vth,  g_Vth);
    cudaGetSymbolAddress((void**)&Sh,   g_Sh);
    cudaGetSymbolAddress((void**)&Ph,   g_Ph);

    cudaFuncSetAttribute(gemm_proj,     cudaFuncAttributeMaxDynamicSharedMemorySize, SMEM_PROJ);
    cudaFuncSetAttribute(gemm_att<1,2>, cudaFuncAttributeMaxDynamicSharedMemorySize, SMEM_ATT);
    cudaFuncSetAttribute(gemm_att<2,0>, cudaFuncAttributeMaxDynamicSharedMemorySize, SMEM_ATT);

    // --- Convert x; transpose weights (one batched launch) ---
    {
        cvt_hi<<<1024, 256>>>(x, xh, (long)NTOK * DIM / 4);
        dim3 tg(DIM / 32, DIM / 32, 3);
        dim3 tb(32, 8);
        transpose_w<<<tg, tb>>>(Qw, Kw, Vw, Wqkh, Wvh);
    }

    // --- Fused Q+K projection: [NTOK,1024] @ [2048,1024]^T ---
    {
        dim3 grid(2048 / 128, NTOK / 256, 1);
        gemm_proj<<<grid, 512, SMEM_PROJ>>>(xh, Wqkh, QKh, DIM, DIM, DIM, 2048);
    }

    // --- V^T projection: Vt[D,NTOK] = Wvh @ xh^T ---
    {
        dim3 grid(NTOK / 128, DIM / 256, 1);
        gemm_proj<<<grid, 512, SMEM_PROJ>>>(Wvh, xh, Vth, DIM, DIM, DIM, NTOK);
    }

    // --- Scores = Qh @ Kh^T per batch (causal skip, heavy rows first) ---
    {
        dim3 grid(SEQ / 128, SEQ / 128, BATCH);
        gemm_att<1,2><<<grid, 256, SMEM_ATT>>>(QKh, QKh + 1024,
                                               nullptr, Sh,
                                               DIM, 2048, 2048, SEQ,
                                               (long)SEQ * 2048, (long)SEQ * 2048,
                                               (long)SEQ * SEQ);
    }

    // --- Softmax: fp16 raw scores -> fp16 probs (vectorized) ---
    softmax_causal<<<dim3(SEQ, BATCH, 1), 256>>>(Sh, Ph);

    // --- Out = Ph @ Vth^T per batch, K clamped, heavy rows first ---
    {
        dim3 grid(DIM / 128, SEQ / 128, BATCH);
        gemm_att<2,0><<<grid, 256, SMEM_ATT>>>(Ph, Vth,
                                               out, nullptr,
                                               SEQ, SEQ, NTOK, DIM,
                                               (long)SEQ * SEQ, SEQ,
                                               (long)SEQ * DIM);
    }
}